// round 9
// baseline (speedup 1.0000x reference)
// Re-run of R8 design (LDSM fragment loads + 8-warp gemmA). R8 bench died in
// infra ("container failed twice") with no compile/run signal; source audit
// found no illegal PTX for sm_100 and no smem/scratch overrun, so this is a
// deliberate resubmission, not a blind change.
#include <cuda_runtime.h>
#include <cuda_bf16.h>

// Problem constants.
static constexpr int B_    = 4096;
static constexpr int NPRE  = 16384;
static constexpr int NPOST = 16384;
static constexpr int R_    = 32;
static constexpr int SPLITK = 32;
static constexpr int KRANGE = NPRE / SPLITK;   // 512
static constexpr int CHUNK  = 32;
static constexpr int NCHUNK = KRANGE / CHUNK;  // 16

// Scratch (__device__ globals; no allocations allowed).
__device__ float    g_Zpart[SPLITK * B_ * R_];     // 16 MB [split][b][r] fp32
__device__ unsigned g_Vphi[(NPRE / 2) * R_];       // 1 MB  V packed bf16x2, [kp][n]
__device__ unsigned g_Vplo[(NPRE / 2) * R_];       // 1 MB
__device__ unsigned g_Utphi[(R_ / 2) * NPOST];     // 1 MB  U^T packed, [rp][n]
__device__ unsigned g_Utplo[(R_ / 2) * NPOST];     // 1 MB
__device__ unsigned g_Zphi[B_ * (R_ / 2)];         // 256 KB Z packed, [b][rp]
__device__ unsigned g_Zplo[B_ * (R_ / 2)];         // 256 KB

// ---------------------------------------------------------------------------
// bf16 helpers + mma.sync m16n8k16 + ldmatrix (baseline PTX, plain sm_100).
// ---------------------------------------------------------------------------
__device__ __forceinline__ void split_bf(float x, float& hi, float& lo) {
    __nv_bfloat16 h = __float2bfloat16_rn(x);
    hi = __bfloat162float(h);
    lo = x - hi;
}
__device__ __forceinline__ unsigned pack2(float x0, float x1) {  // x0 -> low half
    __nv_bfloat162 t = __floats2bfloat162_rn(x0, x1);
    return *reinterpret_cast<unsigned*>(&t);
}
__device__ __forceinline__ void mma16(float* d, const unsigned* a, const unsigned* b) {
    asm volatile(
        "mma.sync.aligned.m16n8k16.row.col.f32.bf16.bf16.f32 "
        "{%0,%1,%2,%3}, {%4,%5,%6,%7}, {%8,%9}, {%0,%1,%2,%3};"
        : "+f"(d[0]), "+f"(d[1]), "+f"(d[2]), "+f"(d[3])
        : "r"(a[0]), "r"(a[1]), "r"(a[2]), "r"(a[3]), "r"(b[0]), "r"(b[1]));
}
__device__ __forceinline__ void ldsm_x4(unsigned* r, unsigned addr) {
    asm volatile("ldmatrix.sync.aligned.m8n8.x4.shared.b16 {%0,%1,%2,%3}, [%4];"
                 : "=r"(r[0]), "=r"(r[1]), "=r"(r[2]), "=r"(r[3]) : "r"(addr));
}
__device__ __forceinline__ unsigned smem_u32(const void* p) {
    unsigned a;
    asm("{ .reg .u64 t; cvta.to.shared.u64 t, %1; cvt.u32.u64 %0, t; }"
        : "=r"(a) : "l"(p));
    return a;
}

// ---------------------------------------------------------------------------
// Pre-passes: build packed bf16x2 hi/lo operand tensors.
// ---------------------------------------------------------------------------
__global__ void splitV(const float* __restrict__ V) {
    int g = blockIdx.x * blockDim.x + threadIdx.x;  // over (NPRE/2)*R_
    int kp = g >> 5, n = g & 31;
    float x0 = V[(size_t)(2 * kp) * R_ + n];
    float x1 = V[(size_t)(2 * kp + 1) * R_ + n];
    float h0, l0, h1, l1;
    split_bf(x0, h0, l0);
    split_bf(x1, h1, l1);
    g_Vphi[g] = pack2(h0, h1);
    g_Vplo[g] = pack2(l0, l1);
}
__global__ void transU(const float* __restrict__ U) {
    int g = blockIdx.x * blockDim.x + threadIdx.x;  // over 16*NPOST
    int rp = g >> 14, n = g & (NPOST - 1);
    float2 u = *reinterpret_cast<const float2*>(&U[(size_t)n * R_ + 2 * rp]);
    float h0, l0, h1, l1;
    split_bf(u.x, h0, l0);
    split_bf(u.y, h1, l1);
    g_Utphi[g] = pack2(h0, h1);
    g_Utplo[g] = pack2(l0, l1);
}
__global__ void reduceZ() {
    int g = blockIdx.x * blockDim.x + threadIdx.x;  // over B_*16
    int b = g >> 4, rp = g & 15;
    float2 s = make_float2(0.f, 0.f);
#pragma unroll
    for (int sp = 0; sp < SPLITK; sp++) {
        float2 v = *reinterpret_cast<const float2*>(
            &g_Zpart[(size_t)sp * B_ * R_ + (size_t)b * R_ + 2 * rp]);
        s.x += v.x;
        s.y += v.y;
    }
    float h0, l0, h1, l1;
    split_bf(s.x, h0, l0);
    split_bf(s.y, h1, l1);
    g_Zphi[g] = pack2(h0, h1);
    g_Zplo[g] = pack2(l0, l1);
}

// ---------------------------------------------------------------------------
// GEMM1: Zpart[split] = S[:, range] @ V[range, :]
// Tile 256 rows x 32 n, 256 threads (8 warps), 3-term bf16, A via ldmatrix.
// A smem words [m][20] (row stride 80B: ldmatrix rows partition all banks);
// B smem words [kp][36]. Register prefetch of the next 32-k chunk.
// ---------------------------------------------------------------------------
__global__ __launch_bounds__(256) void gemmA(const float* __restrict__ S) {
    __shared__ unsigned sAhi[256 * 20];
    __shared__ unsigned sAlo[256 * 20];
    __shared__ unsigned sBhi[16 * 36];
    __shared__ unsigned sBlo[16 * 36];

    const int tid = threadIdx.x, wid = tid >> 5, lane = tid & 31;
    const int gq = lane >> 2, tg = lane & 3;
    const int m0 = blockIdx.x * 256;
    const int k0 = blockIdx.y * KRANGE;

    // ldmatrix per-lane address components.
    const int rowoff = ((lane >> 3) & 1) * 8 + (lane & 7);
    const int segoff = ((lane >> 4) & 1) * 16;   // bytes
    const unsigned baseAhi = smem_u32(sAhi);
    const unsigned baseAlo = smem_u32(sAlo);

    float acc[2][4][4];
#pragma unroll
    for (int mt = 0; mt < 2; mt++)
#pragma unroll
        for (int nt = 0; nt < 4; nt++)
#pragma unroll
            for (int q = 0; q < 4; q++) acc[mt][nt][q] = 0.f;

    // Prefetch chunk 0.
    float4 pS[8];
    uint4 pBh, pBl;
#pragma unroll
    for (int i = 0; i < 8; i++) {
        int idx = tid + i * 256, row = idx >> 3, kq = idx & 7;
        pS[i] = *reinterpret_cast<const float4*>(
            &S[(size_t)(m0 + row) * NPRE + k0 + kq * 4]);
    }
    if (tid < 128) {
        size_t src = (size_t)((k0 >> 1) + (tid >> 3)) * R_ + (tid & 7) * 4;
        pBh = *reinterpret_cast<const uint4*>(&g_Vphi[src]);
        pBl = *reinterpret_cast<const uint4*>(&g_Vplo[src]);
    }

    for (int c = 0; c < NCHUNK; c++) {
        // Commit prefetched chunk (split S -> bf16 hi/lo, pack pairs along k).
#pragma unroll
        for (int i = 0; i < 8; i++) {
            int idx = tid + i * 256, row = idx >> 3, kq = idx & 7;
            float4 v = pS[i];
            float h0, l0, h1, l1, h2, l2, h3, l3;
            split_bf(v.x, h0, l0);
            split_bf(v.y, h1, l1);
            split_bf(v.z, h2, l2);
            split_bf(v.w, h3, l3);
            unsigned off = row * 20 + kq * 2;
            *reinterpret_cast<uint2*>(&sAhi[off]) =
                make_uint2(pack2(h0, h1), pack2(h2, h3));
            *reinterpret_cast<uint2*>(&sAlo[off]) =
                make_uint2(pack2(l0, l1), pack2(l2, l3));
        }
        if (tid < 128) {
            unsigned off = (tid >> 3) * 36 + (tid & 7) * 4;
            *reinterpret_cast<uint4*>(&sBhi[off]) = pBh;
            *reinterpret_cast<uint4*>(&sBlo[off]) = pBl;
        }
        __syncthreads();

        // Prefetch next chunk (overlaps fragment loads + MMA below).
        if (c + 1 < NCHUNK) {
            const int kn = k0 + (c + 1) * CHUNK;
#pragma unroll
            for (int i = 0; i < 8; i++) {
                int idx = tid + i * 256, row = idx >> 3, kq = idx & 7;
                pS[i] = *reinterpret_cast<const float4*>(
                    &S[(size_t)(m0 + row) * NPRE + kn + kq * 4]);
            }
            if (tid < 128) {
                size_t src = (size_t)((kn >> 1) + (tid >> 3)) * R_ + (tid & 7) * 4;
                pBh = *reinterpret_cast<const uint4*>(&g_Vphi[src]);
                pBl = *reinterpret_cast<const uint4*>(&g_Vplo[src]);
            }
        }

#pragma unroll
        for (int ks = 0; ks < 2; ks++) {
            unsigned bh[4][2], bl[4][2];
#pragma unroll
            for (int nt = 0; nt < 4; nt++) {
                bh[nt][0] = sBhi[(ks * 8 + tg) * 36 + nt * 8 + gq];
                bh[nt][1] = sBhi[(ks * 8 + tg + 4) * 36 + nt * 8 + gq];
                bl[nt][0] = sBlo[(ks * 8 + tg) * 36 + nt * 8 + gq];
                bl[nt][1] = sBlo[(ks * 8 + tg + 4) * 36 + nt * 8 + gq];
            }
#pragma unroll
            for (int mt = 0; mt < 2; mt++) {
                const unsigned rb = (wid * 32 + mt * 16 + rowoff) * 80 + ks * 32 + segoff;
                unsigned ah[4], al[4];
                ldsm_x4(ah, baseAhi + rb);
                ldsm_x4(al, baseAlo + rb);
#pragma unroll
                for (int nt = 0; nt < 4; nt++) {
                    mma16(acc[mt][nt], ah, bh[nt]);
                    mma16(acc[mt][nt], ah, bl[nt]);
                    mma16(acc[mt][nt], al, bh[nt]);
                }
            }
        }
        __syncthreads();
    }

    // Epilogue: fragment-direct fp32 stores (small tensor).
    float* out = &g_Zpart[(size_t)blockIdx.y * B_ * R_];
#pragma unroll
    for (int mt = 0; mt < 2; mt++) {
        const int row = m0 + wid * 32 + mt * 16 + gq;
#pragma unroll
        for (int nt = 0; nt < 4; nt++) {
            const int col = nt * 8 + tg * 2;
            *reinterpret_cast<float2*>(&out[(size_t)row * R_ + col]) =
                make_float2(acc[mt][nt][0], acc[mt][nt][1]);
            *reinterpret_cast<float2*>(&out[(size_t)(row + 8) * R_ + col]) =
                make_float2(acc[mt][nt][2], acc[mt][nt][3]);
        }
    }
}

// ---------------------------------------------------------------------------
// GEMM2: Y = Z @ U^T. Tile 128b x 128n, 256 threads (warps 2 x 4), K=32
// single shot, 3-term bf16, A via ldmatrix. Direct fragment stores.
// ---------------------------------------------------------------------------
__global__ __launch_bounds__(256) void gemmB(float* __restrict__ Y) {
    __shared__ unsigned sZhi[128 * 20];
    __shared__ unsigned sZlo[128 * 20];
    __shared__ unsigned sUhi[16 * 132];
    __shared__ unsigned sUlo[16 * 132];

    const int tid = threadIdx.x, wid = tid >> 5, lane = tid & 31;
    const int gq = lane >> 2, tg = lane & 3;
    const int wm = wid >> 2, wn = wid & 3;
    const int n0 = blockIdx.x * 128;
    const int b0 = blockIdx.y * 128;

    const int rowoff = ((lane >> 3) & 1) * 8 + (lane & 7);
    const int segoff = ((lane >> 4) & 1) * 16;
    const unsigned baseZhi = smem_u32(sZhi);
    const unsigned baseZlo = smem_u32(sZlo);

    // Stage Z tile: 2048 words per buffer = 512 uint4, 2 per thread.
#pragma unroll
    for (int p = 0; p < 2; p++) {
        int idx = tid + p * 256, row = idx >> 2, c4 = (idx & 3) * 4;
        size_t src = (size_t)(b0 + row) * 16 + c4;
        *reinterpret_cast<uint4*>(&sZhi[row * 20 + c4]) =
            *reinterpret_cast<const uint4*>(&g_Zphi[src]);
        *reinterpret_cast<uint4*>(&sZlo[row * 20 + c4]) =
            *reinterpret_cast<const uint4*>(&g_Zplo[src]);
    }
    // Stage U^T tile: [16 rp][128 n] words.
#pragma unroll
    for (int p = 0; p < 2; p++) {
        int idx = tid + p * 256, rp = idx >> 5, n4 = (idx & 31) * 4;
        size_t src = (size_t)rp * NPOST + n0 + n4;
        *reinterpret_cast<uint4*>(&sUhi[rp * 132 + n4]) =
            *reinterpret_cast<const uint4*>(&g_Utphi[src]);
        *reinterpret_cast<uint4*>(&sUlo[rp * 132 + n4]) =
            *reinterpret_cast<const uint4*>(&g_Utplo[src]);
    }
    __syncthreads();

    float acc[4][4][4];
#pragma unroll
    for (int mt = 0; mt < 4; mt++)
#pragma unroll
        for (int nt = 0; nt < 4; nt++)
#pragma unroll
            for (int q = 0; q < 4; q++) acc[mt][nt][q] = 0.f;

#pragma unroll
    for (int ks = 0; ks < 2; ks++) {
        unsigned bh[4][2], bl[4][2];
#pragma unroll
        for (int nt = 0; nt < 4; nt++) {
            const int nc = wn * 32 + nt * 8 + gq;
            bh[nt][0] = sUhi[(ks * 8 + tg) * 132 + nc];
            bh[nt][1] = sUhi[(ks * 8 + tg + 4) * 132 + nc];
            bl[nt][0] = sUlo[(ks * 8 + tg) * 132 + nc];
            bl[nt][1] = sUlo[(ks * 8 + tg + 4) * 132 + nc];
        }
#pragma unroll
        for (int mt = 0; mt < 4; mt++) {
            const unsigned rb = (wm * 64 + mt * 16 + rowoff) * 80 + ks * 32 + segoff;
            unsigned ah[4], al[4];
            ldsm_x4(ah, baseZhi + rb);
            ldsm_x4(al, baseZlo + rb);
#pragma unroll
            for (int nt = 0; nt < 4; nt++) {
                mma16(acc[mt][nt], ah, bh[nt]);
                mma16(acc[mt][nt], ah, bl[nt]);
                mma16(acc[mt][nt], al, bh[nt]);
            }
        }
    }

    // Direct fragment stores: 4 lanes x float2 fill each 32B sector.
#pragma unroll
    for (int mt = 0; mt < 4; mt++) {
        const int row = b0 + wm * 64 + mt * 16 + gq;
#pragma unroll
        for (int nt = 0; nt < 4; nt++) {
            const int col = n0 + wn * 32 + nt * 8 + tg * 2;
            *reinterpret_cast<float2*>(&Y[(size_t)row * NPOST + col]) =
                make_float2(acc[mt][nt][0], acc[mt][nt][1]);
            *reinterpret_cast<float2*>(&Y[(size_t)(row + 8) * NPOST + col]) =
                make_float2(acc[mt][nt][2], acc[mt][nt][3]);
        }
    }
}

// ---------------------------------------------------------------------------
// Entry point. Inputs: spikes, U, V, mask_* (masks unused by the reference).
// ---------------------------------------------------------------------------
extern "C" void kernel_launch(void* const* d_in, const int* in_sizes, int n_in,
                              void* d_out, int out_size) {
    const float* spikes = (const float*)d_in[0];
    const float* U      = (const float*)d_in[1];
    const float* V      = (const float*)d_in[2];
    float* Y            = (float*)d_out;

    splitV<<<((NPRE / 2) * R_) / 256, 256>>>(V);
    transU<<<((R_ / 2) * NPOST) / 256, 256>>>(U);
    gemmA<<<dim3(B_ / 256, SPLITK), 256>>>(spikes);
    reduceZ<<<(B_ * (R_ / 2)) / 256, 256>>>();
    gemmB<<<dim3(NPOST / 128, B_ / 128), 256>>>(Y);
}

// round 10
// speedup vs baseline: 1.3783x; 1.3783x over previous
#include <cuda_runtime.h>
#include <cuda_fp16.h>

// Problem constants.
static constexpr int B_    = 4096;
static constexpr int NPRE  = 16384;
static constexpr int NPOST = 16384;
static constexpr int R_    = 32;
static constexpr int SPLITK = 32;
static constexpr int KRANGE = NPRE / SPLITK;   // 512
static constexpr int CHUNK  = 32;
static constexpr int NCHUNK = KRANGE / CHUNK;  // 16

// Scratch (__device__ globals; no allocations allowed).
__device__ float    g_Zpart[SPLITK * B_ * R_];  // 16 MB [split][b][r] fp32
__device__ unsigned g_Vh[(NPRE / 2) * R_];      // 1 MB  V packed f16x2 (pairs along k), [kp][n]
__device__ unsigned g_Uth[(R_ / 2) * NPOST];    // 1 MB  U^T packed (pairs along r), [rp][n]
__device__ unsigned g_Zh[B_ * (R_ / 2)];        // 256 KB Z packed, [b][rp]

// ---------------------------------------------------------------------------
// fp16 helpers + mma.sync m16n8k16 + ldmatrix (baseline PTX, plain sm_100).
// ---------------------------------------------------------------------------
__device__ __forceinline__ unsigned pack2h(float x0, float x1) {  // x0 -> low half
    __half2 t = __floats2half2_rn(x0, x1);
    return *reinterpret_cast<unsigned*>(&t);
}
__device__ __forceinline__ void mma16(float* d, const unsigned* a, const unsigned* b) {
    asm volatile(
        "mma.sync.aligned.m16n8k16.row.col.f32.f16.f16.f32 "
        "{%0,%1,%2,%3}, {%4,%5,%6,%7}, {%8,%9}, {%0,%1,%2,%3};"
        : "+f"(d[0]), "+f"(d[1]), "+f"(d[2]), "+f"(d[3])
        : "r"(a[0]), "r"(a[1]), "r"(a[2]), "r"(a[3]), "r"(b[0]), "r"(b[1]));
}
__device__ __forceinline__ void ldsm_x4(unsigned* r, unsigned addr) {
    asm volatile("ldmatrix.sync.aligned.m8n8.x4.shared.b16 {%0,%1,%2,%3}, [%4];"
                 : "=r"(r[0]), "=r"(r[1]), "=r"(r[2]), "=r"(r[3]) : "r"(addr));
}
__device__ __forceinline__ unsigned smem_u32(const void* p) {
    unsigned a;
    asm("{ .reg .u64 t; cvta.to.shared.u64 t, %1; cvt.u32.u64 %0, t; }"
        : "=r"(a) : "l"(p));
    return a;
}

// ---------------------------------------------------------------------------
// Pre-passes.
// ---------------------------------------------------------------------------
__global__ void prepV(const float* __restrict__ V) {
    int g = blockIdx.x * blockDim.x + threadIdx.x;  // over (NPRE/2)*R_
    int kp = g >> 5, n = g & 31;
    g_Vh[g] = pack2h(V[(size_t)(2 * kp) * R_ + n],
                     V[(size_t)(2 * kp + 1) * R_ + n]);
}
// One thread per U row: coalesced 128B reads; per-rp write streams coalesced
// across threads (fixes the old stride-128B gather).
__global__ void prepU(const float* __restrict__ U) {
    int n = blockIdx.x * blockDim.x + threadIdx.x;  // 0..NPOST-1
    float4 u[8];
#pragma unroll
    for (int i = 0; i < 8; i++)
        u[i] = *reinterpret_cast<const float4*>(&U[(size_t)n * R_ + i * 4]);
    const float* uf = reinterpret_cast<const float*>(u);
#pragma unroll
    for (int rp = 0; rp < 16; rp++)
        g_Uth[(size_t)rp * NPOST + n] = pack2h(uf[2 * rp], uf[2 * rp + 1]);
}
__global__ void reduceZ() {
    int g = blockIdx.x * blockDim.x + threadIdx.x;  // over B_*16
    int b = g >> 4, rp = g & 15;
    float2 s = make_float2(0.f, 0.f);
#pragma unroll
    for (int sp = 0; sp < SPLITK; sp++) {
        float2 v = *reinterpret_cast<const float2*>(
            &g_Zpart[(size_t)sp * B_ * R_ + (size_t)b * R_ + 2 * rp]);
        s.x += v.x;
        s.y += v.y;
    }
    g_Zh[g] = pack2h(s.x, s.y);
}

// ---------------------------------------------------------------------------
// GEMM1: Zpart[split] = S[:, range] @ V[range, :]
// Tile 256 rows x 32 n, 256 threads (8 warps), single-term fp16.
// A smem words [m][20] (80B row stride: ldmatrix rows partition all banks);
// B smem words [kp][36]. Register prefetch of the next 32-k chunk.
// ---------------------------------------------------------------------------
__global__ __launch_bounds__(256) void gemmA(const float* __restrict__ S) {
    __shared__ unsigned sA[256 * 20];
    __shared__ unsigned sB[16 * 36];

    const int tid = threadIdx.x, wid = tid >> 5, lane = tid & 31;
    const int gq = lane >> 2, tg = lane & 3;
    const int m0 = blockIdx.x * 256;
    const int k0 = blockIdx.y * KRANGE;

    const int rowoff = ((lane >> 3) & 1) * 8 + (lane & 7);
    const int segoff = ((lane >> 4) & 1) * 16;   // bytes
    const unsigned baseA = smem_u32(sA);

    float acc[2][4][4];
#pragma unroll
    for (int mt = 0; mt < 2; mt++)
#pragma unroll
        for (int nt = 0; nt < 4; nt++)
#pragma unroll
            for (int q = 0; q < 4; q++) acc[mt][nt][q] = 0.f;

    // Prefetch chunk 0.
    float4 pS[8];
    uint4 pB;
#pragma unroll
    for (int i = 0; i < 8; i++) {
        int idx = tid + i * 256, row = idx >> 3, kq = idx & 7;
        pS[i] = *reinterpret_cast<const float4*>(
            &S[(size_t)(m0 + row) * NPRE + k0 + kq * 4]);
    }
    if (tid < 128) {
        size_t src = (size_t)((k0 >> 1) + (tid >> 3)) * R_ + (tid & 7) * 4;
        pB = *reinterpret_cast<const uint4*>(&g_Vh[src]);
    }

    for (int c = 0; c < NCHUNK; c++) {
        // Commit prefetched chunk: fp32 -> f16x2 (1 cvt per pair).
#pragma unroll
        for (int i = 0; i < 8; i++) {
            int idx = tid + i * 256, row = idx >> 3, kq = idx & 7;
            float4 v = pS[i];
            *reinterpret_cast<uint2*>(&sA[row * 20 + kq * 2]) =
                make_uint2(pack2h(v.x, v.y), pack2h(v.z, v.w));
        }
        if (tid < 128)
            *reinterpret_cast<uint4*>(&sB[(tid >> 3) * 36 + (tid & 7) * 4]) = pB;
        __syncthreads();

        // Prefetch next chunk (overlaps fragment loads + MMA below).
        if (c + 1 < NCHUNK) {
            const int kn = k0 + (c + 1) * CHUNK;
#pragma unroll
            for (int i = 0; i < 8; i++) {
                int idx = tid + i * 256, row = idx >> 3, kq = idx & 7;
                pS[i] = *reinterpret_cast<const float4*>(
                    &S[(size_t)(m0 + row) * NPRE + kn + kq * 4]);
            }
            if (tid < 128) {
                size_t src = (size_t)((kn >> 1) + (tid >> 3)) * R_ + (tid & 7) * 4;
                pB = *reinterpret_cast<const uint4*>(&g_Vh[src]);
            }
        }

#pragma unroll
        for (int ks = 0; ks < 2; ks++) {
            unsigned bf[4][2];
#pragma unroll
            for (int nt = 0; nt < 4; nt++) {
                bf[nt][0] = sB[(ks * 8 + tg) * 36 + nt * 8 + gq];
                bf[nt][1] = sB[(ks * 8 + tg + 4) * 36 + nt * 8 + gq];
            }
#pragma unroll
            for (int mt = 0; mt < 2; mt++) {
                const unsigned rb = (wid * 32 + mt * 16 + rowoff) * 80 + ks * 32 + segoff;
                unsigned af[4];
                ldsm_x4(af, baseA + rb);
#pragma unroll
                for (int nt = 0; nt < 4; nt++)
                    mma16(acc[mt][nt], af, bf[nt]);
            }
        }
        __syncthreads();
    }

    // Epilogue: fragment-direct fp32 stores (small tensor).
    float* out = &g_Zpart[(size_t)blockIdx.y * B_ * R_];
#pragma unroll
    for (int mt = 0; mt < 2; mt++) {
        const int row = m0 + wid * 32 + mt * 16 + gq;
#pragma unroll
        for (int nt = 0; nt < 4; nt++) {
            const int col = nt * 8 + tg * 2;
            *reinterpret_cast<float2*>(&out[(size_t)row * R_ + col]) =
                make_float2(acc[mt][nt][0], acc[mt][nt][1]);
            *reinterpret_cast<float2*>(&out[(size_t)(row + 8) * R_ + col]) =
                make_float2(acc[mt][nt][2], acc[mt][nt][3]);
        }
    }
}

// ---------------------------------------------------------------------------
// GEMM2: Y = Z @ U^T. Tile 128b x 128n, 256 threads (warps 2 x 4), K=32
// single shot, single-term fp16, A via ldmatrix. Direct fragment stores.
// ---------------------------------------------------------------------------
__global__ __launch_bounds__(256) void gemmB(float* __restrict__ Y) {
    __shared__ unsigned sZ[128 * 20];
    __shared__ unsigned sU[16 * 132];

    const int tid = threadIdx.x, wid = tid >> 5, lane = tid & 31;
    const int gq = lane >> 2, tg = lane & 3;
    const int wm = wid >> 2, wn = wid & 3;
    const int n0 = blockIdx.x * 128;
    const int b0 = blockIdx.y * 128;

    const int rowoff = ((lane >> 3) & 1) * 8 + (lane & 7);
    const int segoff = ((lane >> 4) & 1) * 16;
    const unsigned baseZ = smem_u32(sZ);

    // Stage Z tile: 2048 words = 512 uint4, 2 per thread.
#pragma unroll
    for (int p = 0; p < 2; p++) {
        int idx = tid + p * 256, row = idx >> 2, c4 = (idx & 3) * 4;
        *reinterpret_cast<uint4*>(&sZ[row * 20 + c4]) =
            *reinterpret_cast<const uint4*>(&g_Zh[(size_t)(b0 + row) * 16 + c4]);
    }
    // Stage U^T tile: [16 rp][128 n] words.
#pragma unroll
    for (int p = 0; p < 2; p++) {
        int idx = tid + p * 256, rp = idx >> 5, n4 = (idx & 31) * 4;
        *reinterpret_cast<uint4*>(&sU[rp * 132 + n4]) =
            *reinterpret_cast<const uint4*>(&g_Uth[(size_t)rp * NPOST + n0 + n4]);
    }
    __syncthreads();

    float acc[4][4][4];
#pragma unroll
    for (int mt = 0; mt < 4; mt++)
#pragma unroll
        for (int nt = 0; nt < 4; nt++)
#pragma unroll
            for (int q = 0; q < 4; q++) acc[mt][nt][q] = 0.f;

#pragma unroll
    for (int ks = 0; ks < 2; ks++) {
        unsigned bf[4][2];
#pragma unroll
        for (int nt = 0; nt < 4; nt++) {
            const int nc = wn * 32 + nt * 8 + gq;
            bf[nt][0] = sU[(ks * 8 + tg) * 132 + nc];
            bf[nt][1] = sU[(ks * 8 + tg + 4) * 132 + nc];
        }
#pragma unroll
        for (int mt = 0; mt < 4; mt++) {
            const unsigned rb = (wm * 64 + mt * 16 + rowoff) * 80 + ks * 32 + segoff;
            unsigned af[4];
            ldsm_x4(af, baseZ + rb);
#pragma unroll
            for (int nt = 0; nt < 4; nt++)
                mma16(acc[mt][nt], af, bf[nt]);
        }
    }

    // Direct fragment stores: 4 lanes x float2 fill each 32B sector.
#pragma unroll
    for (int mt = 0; mt < 4; mt++) {
        const int row = b0 + wm * 64 + mt * 16 + gq;
#pragma unroll
        for (int nt = 0; nt < 4; nt++) {
            const int col = n0 + wn * 32 + nt * 8 + tg * 2;
            *reinterpret_cast<float2*>(&Y[(size_t)row * NPOST + col]) =
                make_float2(acc[mt][nt][0], acc[mt][nt][1]);
            *reinterpret_cast<float2*>(&Y[(size_t)(row + 8) * NPOST + col]) =
                make_float2(acc[mt][nt][2], acc[mt][nt][3]);
        }
    }
}

// ---------------------------------------------------------------------------
// Entry point. Inputs: spikes, U, V, mask_* (masks unused by the reference).
// ---------------------------------------------------------------------------
extern "C" void kernel_launch(void* const* d_in, const int* in_sizes, int n_in,
                              void* d_out, int out_size) {
    const float* spikes = (const float*)d_in[0];
    const float* U      = (const float*)d_in[1];
    const float* V      = (const float*)d_in[2];
    float* Y            = (float*)d_out;

    prepV<<<((NPRE / 2) * R_) / 256, 256>>>(V);
    prepU<<<NPOST / 256, 256>>>(U);
    gemmA<<<dim3(B_ / 256, SPLITK), 256>>>(spikes);
    reduceZ<<<(B_ * (R_ / 2)) / 256, 256>>>();
    gemmB<<<dim3(NPOST / 128, B_ / 128), 256>>>(Y);
}

// round 11
// speedup vs baseline: 1.4004x; 1.0161x over previous
#include <cuda_runtime.h>
#include <cuda_fp16.h>

// Problem constants.
static constexpr int B_    = 4096;
static constexpr int NPRE  = 16384;
static constexpr int NPOST = 16384;
static constexpr int R_    = 32;
static constexpr int SPLITK = 32;
static constexpr int KRANGE = NPRE / SPLITK;   // 512
static constexpr int CHUNK  = 32;
static constexpr int NCHUNK = KRANGE / CHUNK;  // 16

// Scratch (__device__ globals; no allocations allowed).
__device__ float    g_Zpart[SPLITK * B_ * R_];  // 16 MB [split][b][r] fp32
__device__ unsigned g_Vh[(NPRE / 2) * R_];      // 1 MB  V packed f16x2 (pairs along k), [kp][n]
__device__ unsigned g_Uth[(R_ / 2) * NPOST];    // 1 MB  U^T packed (pairs along r), [rp][n]
__device__ unsigned g_Zh[B_ * (R_ / 2)];        // 256 KB Z packed, [b][rp]

// ---------------------------------------------------------------------------
// fp16 helpers + mma.sync m16n8k16 + ldmatrix (baseline PTX, plain sm_100).
// ---------------------------------------------------------------------------
__device__ __forceinline__ unsigned pack2h(float x0, float x1) {  // x0 -> low half
    __half2 t = __floats2half2_rn(x0, x1);
    return *reinterpret_cast<unsigned*>(&t);
}
__device__ __forceinline__ void mma16(float* d, const unsigned* a, const unsigned* b) {
    asm volatile(
        "mma.sync.aligned.m16n8k16.row.col.f32.f16.f16.f32 "
        "{%0,%1,%2,%3}, {%4,%5,%6,%7}, {%8,%9}, {%0,%1,%2,%3};"
        : "+f"(d[0]), "+f"(d[1]), "+f"(d[2]), "+f"(d[3])
        : "r"(a[0]), "r"(a[1]), "r"(a[2]), "r"(a[3]), "r"(b[0]), "r"(b[1]));
}
__device__ __forceinline__ void ldsm_x4(unsigned* r, unsigned addr) {
    asm volatile("ldmatrix.sync.aligned.m8n8.x4.shared.b16 {%0,%1,%2,%3}, [%4];"
                 : "=r"(r[0]), "=r"(r[1]), "=r"(r[2]), "=r"(r[3]) : "r"(addr));
}
__device__ __forceinline__ unsigned smem_u32(const void* p) {
    unsigned a;
    asm("{ .reg .u64 t; cvta.to.shared.u64 t, %1; cvt.u32.u64 %0, t; }"
        : "=r"(a) : "l"(p));
    return a;
}

// ---------------------------------------------------------------------------
// Pre-passes.
// ---------------------------------------------------------------------------
__global__ void prepV(const float* __restrict__ V) {
    int g = blockIdx.x * blockDim.x + threadIdx.x;  // over (NPRE/2)*R_
    int kp = g >> 5, n = g & 31;
    g_Vh[g] = pack2h(V[(size_t)(2 * kp) * R_ + n],
                     V[(size_t)(2 * kp + 1) * R_ + n]);
}
__global__ void prepU(const float* __restrict__ U) {
    int n = blockIdx.x * blockDim.x + threadIdx.x;  // 0..NPOST-1
    float4 u[8];
#pragma unroll
    for (int i = 0; i < 8; i++)
        u[i] = *reinterpret_cast<const float4*>(&U[(size_t)n * R_ + i * 4]);
    const float* uf = reinterpret_cast<const float*>(u);
#pragma unroll
    for (int rp = 0; rp < 16; rp++)
        g_Uth[(size_t)rp * NPOST + n] = pack2h(uf[2 * rp], uf[2 * rp + 1]);
}
__global__ void reduceZ() {
    int g = blockIdx.x * blockDim.x + threadIdx.x;  // over B_*16
    int b = g >> 4, rp = g & 15;
    float2 s = make_float2(0.f, 0.f);
#pragma unroll
    for (int sp = 0; sp < SPLITK; sp++) {
        float2 v = *reinterpret_cast<const float2*>(
            &g_Zpart[(size_t)sp * B_ * R_ + (size_t)b * R_ + 2 * rp]);
        s.x += v.x;
        s.y += v.y;
    }
    g_Zh[g] = pack2h(s.x, s.y);
}

// ---------------------------------------------------------------------------
// GEMM1: Zpart[split] = S[:, range] @ V[range, :]
// Tile 256 rows x 32 n, 256 threads (8 warps), single-term fp16.
// DOUBLE-BUFFERED smem (one __syncthreads per chunk; STS(c+1) overlaps MMA(c)).
// A smem words [m][20] per buffer (80B row stride); B smem words [kp][36].
// ---------------------------------------------------------------------------
__global__ __launch_bounds__(256) void gemmA(const float* __restrict__ S) {
    __shared__ unsigned sA[2][256 * 20];   // 2 x 20 KB
    __shared__ unsigned sB[2][16 * 36];    // 2 x 2.25 KB

    const int tid = threadIdx.x, wid = tid >> 5, lane = tid & 31;
    const int gq = lane >> 2, tg = lane & 3;
    const int m0 = blockIdx.x * 256;
    const int k0 = blockIdx.y * KRANGE;

    const int rowoff = ((lane >> 3) & 1) * 8 + (lane & 7);
    const int segoff = ((lane >> 4) & 1) * 16;   // bytes
    const unsigned baseA = smem_u32(sA);

    float acc[2][4][4];
#pragma unroll
    for (int mt = 0; mt < 2; mt++)
#pragma unroll
        for (int nt = 0; nt < 4; nt++)
#pragma unroll
            for (int q = 0; q < 4; q++) acc[mt][nt][q] = 0.f;

    // Prefetch chunk 0.
    float4 pS[8];
    uint4 pB;
#pragma unroll
    for (int i = 0; i < 8; i++) {
        int idx = tid + i * 256, row = idx >> 3, kq = idx & 7;
        pS[i] = *reinterpret_cast<const float4*>(
            &S[(size_t)(m0 + row) * NPRE + k0 + kq * 4]);
    }
    if (tid < 128) {
        size_t src = (size_t)((k0 >> 1) + (tid >> 3)) * R_ + (tid & 7) * 4;
        pB = *reinterpret_cast<const uint4*>(&g_Vh[src]);
    }

    for (int c = 0; c < NCHUNK; c++) {
        const int buf = c & 1;
        // Commit prefetched chunk into buffer `buf`. Previous reader of this
        // buffer was MMA(c-2); one barrier (iter c-1's) separates them.
#pragma unroll
        for (int i = 0; i < 8; i++) {
            int idx = tid + i * 256, row = idx >> 3, kq = idx & 7;
            float4 v = pS[i];
            *reinterpret_cast<uint2*>(&sA[buf][row * 20 + kq * 2]) =
                make_uint2(pack2h(v.x, v.y), pack2h(v.z, v.w));
        }
        if (tid < 128)
            *reinterpret_cast<uint4*>(&sB[buf][(tid >> 3) * 36 + (tid & 7) * 4]) = pB;
        __syncthreads();

        // Prefetch next chunk (overlaps the MMA below).
        if (c + 1 < NCHUNK) {
            const int kn = k0 + (c + 1) * CHUNK;
#pragma unroll
            for (int i = 0; i < 8; i++) {
                int idx = tid + i * 256, row = idx >> 3, kq = idx & 7;
                pS[i] = *reinterpret_cast<const float4*>(
                    &S[(size_t)(m0 + row) * NPRE + kn + kq * 4]);
            }
            if (tid < 128) {
                size_t src = (size_t)((kn >> 1) + (tid >> 3)) * R_ + (tid & 7) * 4;
                pB = *reinterpret_cast<const uint4*>(&g_Vh[src]);
            }
        }

        const unsigned bufA = baseA + buf * (256 * 20 * 4);
#pragma unroll
        for (int ks = 0; ks < 2; ks++) {
            unsigned bf[4][2];
#pragma unroll
            for (int nt = 0; nt < 4; nt++) {
                bf[nt][0] = sB[buf][(ks * 8 + tg) * 36 + nt * 8 + gq];
                bf[nt][1] = sB[buf][(ks * 8 + tg + 4) * 36 + nt * 8 + gq];
            }
#pragma unroll
            for (int mt = 0; mt < 2; mt++) {
                const unsigned rb = (wid * 32 + mt * 16 + rowoff) * 80 + ks * 32 + segoff;
                unsigned af[4];
                ldsm_x4(af, bufA + rb);
#pragma unroll
                for (int nt = 0; nt < 4; nt++)
                    mma16(acc[mt][nt], af, bf[nt]);
            }
        }
    }

    // Epilogue: fragment-direct fp32 stores (small tensor).
    float* out = &g_Zpart[(size_t)blockIdx.y * B_ * R_];
#pragma unroll
    for (int mt = 0; mt < 2; mt++) {
        const int row = m0 + wid * 32 + mt * 16 + gq;
#pragma unroll
        for (int nt = 0; nt < 4; nt++) {
            const int col = nt * 8 + tg * 2;
            *reinterpret_cast<float2*>(&out[(size_t)row * R_ + col]) =
                make_float2(acc[mt][nt][0], acc[mt][nt][1]);
            *reinterpret_cast<float2*>(&out[(size_t)(row + 8) * R_ + col]) =
                make_float2(acc[mt][nt][2], acc[mt][nt][3]);
        }
    }
}

// ---------------------------------------------------------------------------
// GEMM2: Y = Z @ U^T. Each CTA: one 128-b tile x FOUR consecutive 128-n
// subtiles (Z resident in smem; U double-buffered; stores of subtile t
// overlap staging/MMA of subtile t+1). 256 threads, warps 2 x 4.
// ---------------------------------------------------------------------------
__global__ __launch_bounds__(256) void gemmB(float* __restrict__ Y) {
    __shared__ unsigned sZ[128 * 20];      // 10 KB, loaded once
    __shared__ unsigned sU[2][16 * 132];   // 2 x 8.25 KB

    const int tid = threadIdx.x, wid = tid >> 5, lane = tid & 31;
    const int gq = lane >> 2, tg = lane & 3;
    const int wm = wid >> 2, wn = wid & 3;
    const int nbase = blockIdx.x * 512;
    const int b0    = blockIdx.y * 128;

    const int rowoff = ((lane >> 3) & 1) * 8 + (lane & 7);
    const int segoff = ((lane >> 4) & 1) * 16;
    const unsigned baseZ = smem_u32(sZ);

    // Per-thread U staging geometry (2 uint4 per subtile).
    const int urp0 = tid >> 5, un4 = (lane)*4;  // idx p=0: rp=tid>>5
    (void)urp0; (void)un4;

    // Prefetch U subtile 0.
    uint4 pU[2];
#pragma unroll
    for (int p = 0; p < 2; p++) {
        int idx = tid + p * 256, rp = idx >> 5, n4 = (idx & 31) * 4;
        pU[p] = *reinterpret_cast<const uint4*>(&g_Uth[(size_t)rp * NPOST + nbase + n4]);
    }
    // Stage Z tile once.
#pragma unroll
    for (int p = 0; p < 2; p++) {
        int idx = tid + p * 256, row = idx >> 2, c4 = (idx & 3) * 4;
        *reinterpret_cast<uint4*>(&sZ[row * 20 + c4]) =
            *reinterpret_cast<const uint4*>(&g_Zh[(size_t)(b0 + row) * 16 + c4]);
    }

    for (int t = 0; t < 4; t++) {
        const int buf = t & 1;
        const int n0 = nbase + t * 128;
        // Commit U subtile t. Previous reader of this buffer: subtile t-2's
        // fragment loads, separated by the barrier of iter t-1.
#pragma unroll
        for (int p = 0; p < 2; p++) {
            int idx = tid + p * 256, rp = idx >> 5, n4 = (idx & 31) * 4;
            *reinterpret_cast<uint4*>(&sU[buf][rp * 132 + n4]) = pU[p];
        }
        __syncthreads();   // also covers sZ on t==0

        // Prefetch next U subtile (overlaps MMA + stores below).
        if (t + 1 < 4) {
#pragma unroll
            for (int p = 0; p < 2; p++) {
                int idx = tid + p * 256, rp = idx >> 5, n4 = (idx & 31) * 4;
                pU[p] = *reinterpret_cast<const uint4*>(
                    &g_Uth[(size_t)rp * NPOST + nbase + (t + 1) * 128 + n4]);
            }
        }

        float acc[4][4][4];
#pragma unroll
        for (int mt = 0; mt < 4; mt++)
#pragma unroll
            for (int nt = 0; nt < 4; nt++)
#pragma unroll
                for (int q = 0; q < 4; q++) acc[mt][nt][q] = 0.f;

#pragma unroll
        for (int ks = 0; ks < 2; ks++) {
            unsigned bf[4][2];
#pragma unroll
            for (int nt = 0; nt < 4; nt++) {
                const int nc = wn * 32 + nt * 8 + gq;
                bf[nt][0] = sU[buf][(ks * 8 + tg) * 132 + nc];
                bf[nt][1] = sU[buf][(ks * 8 + tg + 4) * 132 + nc];
            }
#pragma unroll
            for (int mt = 0; mt < 4; mt++) {
                const unsigned rb = (wm * 64 + mt * 16 + rowoff) * 80 + ks * 32 + segoff;
                unsigned af[4];
                ldsm_x4(af, baseZ + rb);
#pragma unroll
                for (int nt = 0; nt < 4; nt++)
                    mma16(acc[mt][nt], af, bf[nt]);
            }
        }

        // Stores for subtile t (overlap next iteration's staging/MMA).
#pragma unroll
        for (int mt = 0; mt < 4; mt++) {
            const int row = b0 + wm * 64 + mt * 16 + gq;
#pragma unroll
            for (int nt = 0; nt < 4; nt++) {
                const int col = n0 + wn * 32 + nt * 8 + tg * 2;
                *reinterpret_cast<float2*>(&Y[(size_t)row * NPOST + col]) =
                    make_float2(acc[mt][nt][0], acc[mt][nt][1]);
                *reinterpret_cast<float2*>(&Y[(size_t)(row + 8) * NPOST + col]) =
                    make_float2(acc[mt][nt][2], acc[mt][nt][3]);
            }
        }
    }
}

// ---------------------------------------------------------------------------
// Entry point. Inputs: spikes, U, V, mask_* (masks unused by the reference).
// ---------------------------------------------------------------------------
extern "C" void kernel_launch(void* const* d_in, const int* in_sizes, int n_in,
                              void* d_out, int out_size) {
    const float* spikes = (const float*)d_in[0];
    const float* U      = (const float*)d_in[1];
    const float* V      = (const float*)d_in[2];
    float* Y            = (float*)d_out;

    prepV<<<((NPRE / 2) * R_) / 256, 256>>>(V);
    prepU<<<NPOST / 256, 256>>>(U);
    gemmA<<<dim3(B_ / 256, SPLITK), 256>>>(spikes);
    reduceZ<<<(B_ * (R_ / 2)) / 256, 256>>>();
    gemmB<<<dim3(NPOST / 512, B_ / 128), 256>>>(Y);
}